// round 9
// baseline (speedup 1.0000x reference)
#include <cuda_runtime.h>
#include <cuda_fp16.h>

// TCLoss, N=2048, D=64.
// y_ijd = LOG2E * log N(z_i,d ; m_j,d, exp(lv_j,d)) = a_jd*z^2 + b_jd*z + g_jd
// out = mean_i [ LN2*( sum_d log2 sum_j 2^y  -  log2sumexp2_j sum_d y ) ]
//
// k0: precompute coeffs (AB float4 (a0,a1,b0,b1), G float2 per (j,dim-pair)).
// k1: persistent main (R6 structure, 2 blocks/SM). Warp owns 2 i's, lane owns
//     dims {2l,2l+1}; 64-j smem tile. y in fp32 FMA. Per-dim exps via
//     ex2.approx.f16x2 (1 MUFU per pair), half2 pair accumulation, fp32 flush
//     each 8-j batch. Scalar S path packs both i's into one half2 per j and
//     runs ONE 9-shuffle multi-value butterfly per 8-j batch, software-
//     pipelined against the next batch's compute; per-lane fp32 online LSE,
//     class-merged once per unit.
// k2: per-i reduction over 32 chunk partials. k3: mean.

#define LOG2E   1.44269504088896340736f
#define LN2     0.69314718055994530942f
#define LOG2PI  1.83787706640934548356f
#define NEG_INF __int_as_float(0xff800000)

#define NPTS    2048
#define DDIM    64
#define TJ      64                   // j's per chunk
#define NCHUNK  (NPTS / TJ)          // 32
#define IPB     16                   // i's per block (8 warps x 2)
#define NGROUP  (NPTS / IPB)         // 128
#define NUNITS  (NGROUP * NCHUNK)    // 4096
#define NBLOCKS 296                  // 148 SMs x 2 resident blocks

// Static scratch (no allocation).
__device__ float4 g_cAB[NPTS * DDIM / 2];       // (a0,a1,b0,b1) per (j, dim-pair)
__device__ float2 g_cG[NPTS * DDIM / 2];        // (g0,g1) per (j, dim-pair)
__device__ float g_psum[NPTS * NCHUNK * DDIM];  // per-(i,chunk) per-dim sums of 2^y
__device__ float g_pm[NPTS * NCHUNK];           // per-(i,chunk) LSE max (log2)
__device__ float g_ps[NPTS * NCHUNK];           // per-(i,chunk) LSE scaled sum
__device__ float g_val[NPTS];                   // per-i result

static __device__ __forceinline__ float ex2f(float x) {
    float r; asm("ex2.approx.ftz.f32 %0, %1;" : "=f"(r) : "f"(x)); return r;
}
static __device__ __forceinline__ float lg2f(float x) {
    float r; asm("lg2.approx.f32 %0, %1;" : "=f"(r) : "f"(x)); return r;
}
// Pack two fp32 -> half2 (single F2FP.PACK), then 2^x on both halves (1 MUFU).
static __device__ __forceinline__ __half2 ex2h2(float x, float y) {
    __half2 h = __floats2half2_rn(x, y);
    __half2 r;
    asm("ex2.approx.f16x2 %0, %1;"
        : "=r"(*reinterpret_cast<unsigned*>(&r))
        : "r"(*reinterpret_cast<const unsigned*>(&h)));
    return r;
}
static __device__ __forceinline__ __half2 h2shfl_xor(__half2 v, int off) {
    unsigned u = *reinterpret_cast<unsigned*>(&v);
    u = __shfl_xor_sync(0xffffffffu, u, off);
    return *reinterpret_cast<__half2*>(&u);
}

// Online base-2 logsumexp update with a single EX2.
static __device__ __forceinline__ void lse_up(float& m, float& s, float S) {
    const float d = S - m;
    const float e = ex2f(-fabsf(d));   // ex2(-inf)=0 handles first call (m=-inf)
    if (d > 0.f) { s = fmaf(s, e, 1.f); m = S; }
    else         { s += e; }
}

// Reduce 8 half2 values (t[k] across 32 lanes) in 9 shuffles; every lane gets
// the 32-lane sum of t[(lane>>2)&7] (both halves = the warp's 2 i's at once).
static __device__ __forceinline__ __half2 mred8h(__half2 t[8], unsigned lane) {
    #pragma unroll
    for (int k = 0; k < 4; ++k) {
        const __half2 send = (lane & 16) ? t[k] : t[k + 4];
        const __half2 keep = (lane & 16) ? t[k + 4] : t[k];
        t[k] = __hadd2(keep, h2shfl_xor(send, 16));
    }
    #pragma unroll
    for (int k = 0; k < 2; ++k) {
        const __half2 send = (lane & 8) ? t[k] : t[k + 2];
        const __half2 keep = (lane & 8) ? t[k + 2] : t[k];
        t[k] = __hadd2(keep, h2shfl_xor(send, 8));
    }
    {
        const __half2 send = (lane & 4) ? t[0] : t[1];
        const __half2 keep = (lane & 4) ? t[1] : t[0];
        t[0] = __hadd2(keep, h2shfl_xor(send, 4));
    }
    __half2 v = t[0];
    v = __hadd2(v, h2shfl_xor(v, 2));
    v = __hadd2(v, h2shfl_xor(v, 1));
    return v;
}

// Merge per-lane (m,s) across the 8 j-classes (lane bits 2..4).
static __device__ __forceinline__ void merge_classes(float& m, float& s) {
    #pragma unroll
    for (int off = 4; off <= 16; off <<= 1) {
        const float mo = __shfl_xor_sync(0xffffffffu, m, off);
        const float so = __shfl_xor_sync(0xffffffffu, s, off);
        const float M  = fmaxf(m, mo);
        s = s * ex2f(m - M) + so * ex2f(mo - M);
        m = M;
    }
}

static __device__ __forceinline__ void coeffs(float mm, float lv,
                                              float& a, float& b, float& g) {
    const float iv = ex2f(-LOG2E * lv);          // exp(-lv)
    const float w  = -0.5f * LOG2E * iv;
    const float t  = w * mm;
    a = w;
    b = -(t + t);
    g = fmaf(t, mm, -0.5f * LOG2E * (lv + LOG2PI));
}

// k0: precompute packed coefficient arrays.
__global__ __launch_bounds__(256)
void tc_coeff_kernel(const float* __restrict__ zmean, const float* __restrict__ zlv)
{
    const int e = blockIdx.x * 256 + threadIdx.x;   // [0, 32768)
    const int j = e >> 4;
    const int f = e & 15;                           // float4 index within row
    const float4 mv = ((const float4*)zmean)[e];
    const float4 lv = ((const float4*)zlv)[e];
    float a0, b0, g0, a1, b1, g1, a2, b2, g2, a3, b3, g3;
    coeffs(mv.x, lv.x, a0, b0, g0);
    coeffs(mv.y, lv.y, a1, b1, g1);
    coeffs(mv.z, lv.z, a2, b2, g2);
    coeffs(mv.w, lv.w, a3, b3, g3);
    g_cAB[(j << 5) + 2 * f]     = make_float4(a0, a1, b0, b1);
    g_cAB[(j << 5) + 2 * f + 1] = make_float4(a2, a3, b2, b3);
    g_cG[(j << 5) + 2 * f]      = make_float2(g0, g1);
    g_cG[(j << 5) + 2 * f + 1]  = make_float2(g2, g3);
}

// k1: main pairwise kernel.
__global__ __launch_bounds__(256, 2)
void tc_main_kernel(const float* __restrict__ z)
{
    __shared__ float4 shAB[TJ * 32];   // 32 KB
    __shared__ float2 shG[TJ * 32];    // 16 KB

    const int tid  = threadIdx.x;
    const int wid  = tid >> 5;
    const unsigned lane = tid & 31;

    for (int u = blockIdx.x; u < NUNITS; u += NBLOCKS) {
        const int ig = u & (NGROUP - 1);
        const int c  = u >> 7;
        const int js = c * TJ;

        __syncthreads();  // previous unit's readers done
        {
            const float4* pab = g_cAB + js * 32;
            const float4* pg  = (const float4*)(g_cG + js * 32);
            #pragma unroll
            for (int e = tid; e < TJ * 32; e += 256)
                shAB[e] = pab[e];
            #pragma unroll
            for (int e = tid; e < TJ * 16; e += 256)
                ((float4*)shG)[e] = pg[e];
        }
        __syncthreads();

        const int i0 = ig * IPB + wid * 2;
        const float2 zva = ((const float2*)z)[i0 * 32 + lane];
        const float2 zvb = ((const float2*)z)[(i0 + 1) * 32 + lane];
        const float zA0 = zva.x, zA1 = zva.y, zB0 = zvb.x, zB1 = zvb.y;
        const float qA0 = zA0 * zA0, qA1 = zA1 * zA1;
        const float qB0 = zB0 * zB0, qB1 = zB1 * zB1;

        float aA0 = 0.f, aA1 = 0.f, aB0 = 0.f, aB1 = 0.f;
        float mA = NEG_INF, sA = 0.f, mB = NEG_INF, sB = 0.f;

        __half2 tP[8];   // previous batch's packed S partials (iA, iB)

        // Software pipeline: compute batch jb, then reduce batch jb-1.
        #pragma unroll
        for (int jb = 0; jb < TJ / 8; ++jb) {
            __half2 tC[8];
            __half2 eqA[4], eqB[4];    // pairwise half2 exp accumulators
            #pragma unroll
            for (int k = 0; k < 8; ++k) {
                const int j = jb * 8 + k;
                const float4 ab = shAB[j * 32 + lane];
                const float2 g  = shG[j * 32 + lane];
                const float yA0 = fmaf(ab.x, qA0, fmaf(ab.z, zA0, g.x));
                const float yA1 = fmaf(ab.y, qA1, fmaf(ab.w, zA1, g.y));
                const float yB0 = fmaf(ab.x, qB0, fmaf(ab.z, zB0, g.x));
                const float yB1 = fmaf(ab.y, qB1, fmaf(ab.w, zB1, g.y));
                const __half2 eA = ex2h2(yA0, yA1);
                const __half2 eB = ex2h2(yB0, yB1);
                if (k & 1) {
                    eqA[k >> 1] = __hadd2(eqA[k >> 1], eA);
                    eqB[k >> 1] = __hadd2(eqB[k >> 1], eB);
                } else {
                    eqA[k >> 1] = eA;
                    eqB[k >> 1] = eB;
                }
                tC[k] = __floats2half2_rn(yA0 + yA1, yB0 + yB1);
            }
            // tree-flush half2 exp partials to fp32 accumulators
            {
                const __half2 rA = __hadd2(__hadd2(eqA[0], eqA[1]),
                                           __hadd2(eqA[2], eqA[3]));
                const __half2 rB = __hadd2(__hadd2(eqB[0], eqB[1]),
                                           __hadd2(eqB[2], eqB[3]));
                const float2 fA = __half22float2(rA);
                const float2 fB = __half22float2(rB);
                aA0 += fA.x; aA1 += fA.y;
                aB0 += fB.x; aB1 += fB.y;
            }
            if (jb > 0) {
                const __half2 S2 = mred8h(tP, lane);
                const float2 fS = __half22float2(S2);
                lse_up(mA, sA, fS.x);
                lse_up(mB, sB, fS.y);
            }
            #pragma unroll
            for (int k = 0; k < 8; ++k) tP[k] = tC[k];
        }
        {
            const __half2 S2 = mred8h(tP, lane);
            const float2 fS = __half22float2(S2);
            lse_up(mA, sA, fS.x);
            lse_up(mB, sB, fS.y);
        }

        ((float2*)g_psum)[(i0 * NCHUNK + c) * 32 + lane]       = make_float2(aA0, aA1);
        ((float2*)g_psum)[((i0 + 1) * NCHUNK + c) * 32 + lane] = make_float2(aB0, aB1);
        merge_classes(mA, sA);
        merge_classes(mB, sB);
        if (lane == 0) {
            g_pm[i0 * NCHUNK + c] = mA;
            g_ps[i0 * NCHUNK + c] = sA;
            g_pm[(i0 + 1) * NCHUNK + c] = mB;
            g_ps[(i0 + 1) * NCHUNK + c] = sB;
        }
    }
}

// k2: one warp per i combines the 32 chunk partials.
__global__ __launch_bounds__(256)
void tc_reduce_i()
{
    const int wid  = threadIdx.x >> 5;
    const int lane = threadIdx.x & 31;
    const int i    = blockIdx.x * 8 + wid;

    float s0 = 0.f, s1 = 0.f;
    const float2* P = (const float2*)g_psum;
    #pragma unroll
    for (int cc = 0; cc < NCHUNK; ++cc) {
        const float2 v = P[(i * NCHUNK + cc) * 32 + lane];
        s0 += v.x; s1 += v.y;
    }
    float t = lg2f(s0) + lg2f(s1);
    #pragma unroll
    for (int off = 16; off; off >>= 1)
        t += __shfl_xor_sync(0xffffffffu, t, off);

    float ml = g_pm[i * NCHUNK + lane];   // NCHUNK==32: one chunk per lane
    float sl = g_ps[i * NCHUNK + lane];
    #pragma unroll
    for (int off = 16; off; off >>= 1) {
        const float mo = __shfl_xor_sync(0xffffffffu, ml, off);
        const float so = __shfl_xor_sync(0xffffffffu, sl, off);
        const float M  = fmaxf(ml, mo);
        sl = sl * ex2f(ml - M) + so * ex2f(mo - M);
        ml = M;
    }

    if (lane == 0)
        g_val[i] = LN2 * (t - (ml + lg2f(sl)));
}

// k3: deterministic final mean (256 threads, shuffle-based).
__global__ __launch_bounds__(256)
void tc_final(float* __restrict__ out)
{
    __shared__ float sm[8];
    const int t = threadIdx.x;
    float v = 0.f;
    #pragma unroll
    for (int k = 0; k < 8; ++k)
        v += g_val[t + k * 256];
    #pragma unroll
    for (int off = 16; off; off >>= 1)
        v += __shfl_xor_sync(0xffffffffu, v, off);
    if ((t & 31) == 0) sm[t >> 5] = v;
    __syncthreads();
    if (t == 0) {
        float r = 0.f;
        #pragma unroll
        for (int k = 0; k < 8; ++k) r += sm[k];
        out[0] = r * (1.0f / (float)NPTS);
    }
}

extern "C" void kernel_launch(void* const* d_in, const int* in_sizes, int n_in,
                              void* d_out, int out_size)
{
    const float* z  = (const float*)d_in[0];
    const float* zm = (const float*)d_in[1];
    const float* zl = (const float*)d_in[2];
    tc_coeff_kernel<<<NPTS * DDIM / 1024, 256>>>(zm, zl);
    tc_main_kernel<<<NBLOCKS, 256>>>(z);
    tc_reduce_i<<<NPTS / 8, 256>>>();
    tc_final<<<1, 256>>>((float*)d_out);
}

// round 10
// speedup vs baseline: 1.1365x; 1.1365x over previous
#include <cuda_runtime.h>
#include <cuda_fp16.h>

// TCLoss, N=2048, D=64.
// y_ijd = LOG2E * log N(z_i,d ; m_j,d, exp(lv_j,d)) = a_jd*z^2 + b_jd*z + g_jd
// out = mean_i [ LN2*( sum_d log2 sum_j 2^y  -  log2sumexp2_j sum_d y ) ]
//
// k0: precompute coeffs (AB float4 (a0,a1,b0,b1), G float2 per (j,dim-pair)).
// k1: persistent main, 3 blocks/SM (6 warps/SMSP hide the butterfly latency;
//     software pipeline removed to fit 84 regs). Warp owns 2 i's, lane owns
//     dims {2l,2l+1}; 64-j smem tile. y in fp32 FMA. Per-dim exps via
//     ex2.approx.f16x2 (1 MUFU per pair), half2 pair accumulation, fp32 flush
//     each 8-j batch. Scalar S path in fp32: per-batch 9-shuffle multi-value
//     butterfly + per-lane online LSE, class-merged once per unit.
// k2: per-i reduction over 32 chunk partials. k3: mean.

#define LOG2E   1.44269504088896340736f
#define LN2     0.69314718055994530942f
#define LOG2PI  1.83787706640934548356f
#define NEG_INF __int_as_float(0xff800000)

#define NPTS    2048
#define DDIM    64
#define TJ      64                   // j's per chunk
#define NCHUNK  (NPTS / TJ)          // 32
#define IPB     16                   // i's per block (8 warps x 2)
#define NGROUP  (NPTS / IPB)         // 128
#define NUNITS  (NGROUP * NCHUNK)    // 4096
#define NBLOCKS 444                  // 148 SMs x 3 resident blocks

// Static scratch (no allocation).
__device__ float4 g_cAB[NPTS * DDIM / 2];       // (a0,a1,b0,b1) per (j, dim-pair)
__device__ float2 g_cG[NPTS * DDIM / 2];        // (g0,g1) per (j, dim-pair)
__device__ float g_psum[NPTS * NCHUNK * DDIM];  // per-(i,chunk) per-dim sums of 2^y
__device__ float g_pm[NPTS * NCHUNK];           // per-(i,chunk) LSE max (log2)
__device__ float g_ps[NPTS * NCHUNK];           // per-(i,chunk) LSE scaled sum
__device__ float g_val[NPTS];                   // per-i result

static __device__ __forceinline__ float ex2f(float x) {
    float r; asm("ex2.approx.ftz.f32 %0, %1;" : "=f"(r) : "f"(x)); return r;
}
static __device__ __forceinline__ float lg2f(float x) {
    float r; asm("lg2.approx.f32 %0, %1;" : "=f"(r) : "f"(x)); return r;
}
// Pack two fp32 -> half2 (single F2FP.PACK), then 2^x on both halves (1 MUFU).
static __device__ __forceinline__ __half2 ex2h2(float x, float y) {
    __half2 h = __floats2half2_rn(x, y);
    __half2 r;
    asm("ex2.approx.f16x2 %0, %1;"
        : "=r"(*reinterpret_cast<unsigned*>(&r))
        : "r"(*reinterpret_cast<const unsigned*>(&h)));
    return r;
}

// Online base-2 logsumexp update with a single EX2.
static __device__ __forceinline__ void lse_up(float& m, float& s, float S) {
    const float d = S - m;
    const float e = ex2f(-fabsf(d));   // ex2(-inf)=0 handles first call (m=-inf)
    if (d > 0.f) { s = fmaf(s, e, 1.f); m = S; }
    else         { s += e; }
}

// Reduce 8 values (t[k], distributed across 32 lanes) in 9 shuffles.
// Returns, on every lane, the full 32-lane sum of t[(lane>>2)&7].
static __device__ __forceinline__ float mred8(float t[8], unsigned lane) {
    #pragma unroll
    for (int k = 0; k < 4; ++k) {
        const float send = (lane & 16) ? t[k] : t[k + 4];
        const float keep = (lane & 16) ? t[k + 4] : t[k];
        t[k] = keep + __shfl_xor_sync(0xffffffffu, send, 16);
    }
    #pragma unroll
    for (int k = 0; k < 2; ++k) {
        const float send = (lane & 8) ? t[k] : t[k + 2];
        const float keep = (lane & 8) ? t[k + 2] : t[k];
        t[k] = keep + __shfl_xor_sync(0xffffffffu, send, 8);
    }
    {
        const float send = (lane & 4) ? t[0] : t[1];
        const float keep = (lane & 4) ? t[1] : t[0];
        t[0] = keep + __shfl_xor_sync(0xffffffffu, send, 4);
    }
    float v = t[0];
    v += __shfl_xor_sync(0xffffffffu, v, 2);
    v += __shfl_xor_sync(0xffffffffu, v, 1);
    return v;
}

// Merge per-lane (m,s) across the 8 j-classes (lane bits 2..4).
static __device__ __forceinline__ void merge_classes(float& m, float& s) {
    #pragma unroll
    for (int off = 4; off <= 16; off <<= 1) {
        const float mo = __shfl_xor_sync(0xffffffffu, m, off);
        const float so = __shfl_xor_sync(0xffffffffu, s, off);
        const float M  = fmaxf(m, mo);
        s = s * ex2f(m - M) + so * ex2f(mo - M);
        m = M;
    }
}

static __device__ __forceinline__ void coeffs(float mm, float lv,
                                              float& a, float& b, float& g) {
    const float iv = ex2f(-LOG2E * lv);          // exp(-lv)
    const float w  = -0.5f * LOG2E * iv;
    const float t  = w * mm;
    a = w;
    b = -(t + t);
    g = fmaf(t, mm, -0.5f * LOG2E * (lv + LOG2PI));
}

// k0: precompute packed coefficient arrays.
__global__ __launch_bounds__(256)
void tc_coeff_kernel(const float* __restrict__ zmean, const float* __restrict__ zlv)
{
    const int e = blockIdx.x * 256 + threadIdx.x;   // [0, 32768)
    const int j = e >> 4;
    const int f = e & 15;                           // float4 index within row
    const float4 mv = ((const float4*)zmean)[e];
    const float4 lv = ((const float4*)zlv)[e];
    float a0, b0, g0, a1, b1, g1, a2, b2, g2, a3, b3, g3;
    coeffs(mv.x, lv.x, a0, b0, g0);
    coeffs(mv.y, lv.y, a1, b1, g1);
    coeffs(mv.z, lv.z, a2, b2, g2);
    coeffs(mv.w, lv.w, a3, b3, g3);
    g_cAB[(j << 5) + 2 * f]     = make_float4(a0, a1, b0, b1);
    g_cAB[(j << 5) + 2 * f + 1] = make_float4(a2, a3, b2, b3);
    g_cG[(j << 5) + 2 * f]      = make_float2(g0, g1);
    g_cG[(j << 5) + 2 * f + 1]  = make_float2(g2, g3);
}

// k1: main pairwise kernel.
__global__ __launch_bounds__(256, 3)
void tc_main_kernel(const float* __restrict__ z)
{
    __shared__ float4 shAB[TJ * 32];   // 32 KB
    __shared__ float2 shG[TJ * 32];    // 16 KB

    const int tid  = threadIdx.x;
    const int wid  = tid >> 5;
    const unsigned lane = tid & 31;

    for (int u = blockIdx.x; u < NUNITS; u += NBLOCKS) {
        const int ig = u & (NGROUP - 1);
        const int c  = u >> 7;
        const int js = c * TJ;

        __syncthreads();  // previous unit's readers done
        {
            const float4* pab = g_cAB + js * 32;
            const float4* pg  = (const float4*)(g_cG + js * 32);
            #pragma unroll
            for (int e = tid; e < TJ * 32; e += 256)
                shAB[e] = pab[e];
            #pragma unroll
            for (int e = tid; e < TJ * 16; e += 256)
                ((float4*)shG)[e] = pg[e];
        }
        __syncthreads();

        const int i0 = ig * IPB + wid * 2;
        const float2 zva = ((const float2*)z)[i0 * 32 + lane];
        const float2 zvb = ((const float2*)z)[(i0 + 1) * 32 + lane];
        const float zA0 = zva.x, zA1 = zva.y, zB0 = zvb.x, zB1 = zvb.y;
        const float qA0 = zA0 * zA0, qA1 = zA1 * zA1;
        const float qB0 = zB0 * zB0, qB1 = zB1 * zB1;

        float aA0 = 0.f, aA1 = 0.f, aB0 = 0.f, aB1 = 0.f;
        float mA = NEG_INF, sA = 0.f, mB = NEG_INF, sB = 0.f;

        #pragma unroll 1
        for (int jb = 0; jb < TJ / 8; ++jb) {
            float tCA[8], tCB[8];
            __half2 eqA[4], eqB[4];    // pairwise half2 exp accumulators
            #pragma unroll
            for (int k = 0; k < 8; ++k) {
                const int j = jb * 8 + k;
                const float4 ab = shAB[j * 32 + lane];
                const float2 g  = shG[j * 32 + lane];
                const float yA0 = fmaf(ab.x, qA0, fmaf(ab.z, zA0, g.x));
                const float yA1 = fmaf(ab.y, qA1, fmaf(ab.w, zA1, g.y));
                const float yB0 = fmaf(ab.x, qB0, fmaf(ab.z, zB0, g.x));
                const float yB1 = fmaf(ab.y, qB1, fmaf(ab.w, zB1, g.y));
                const __half2 eA = ex2h2(yA0, yA1);
                const __half2 eB = ex2h2(yB0, yB1);
                if (k & 1) {
                    eqA[k >> 1] = __hadd2(eqA[k >> 1], eA);
                    eqB[k >> 1] = __hadd2(eqB[k >> 1], eB);
                } else {
                    eqA[k >> 1] = eA;
                    eqB[k >> 1] = eB;
                }
                tCA[k] = yA0 + yA1;
                tCB[k] = yB0 + yB1;
            }
            // tree-flush half2 exp partials to fp32 accumulators
            {
                const __half2 rA = __hadd2(__hadd2(eqA[0], eqA[1]),
                                           __hadd2(eqA[2], eqA[3]));
                const __half2 rB = __hadd2(__hadd2(eqB[0], eqB[1]),
                                           __hadd2(eqB[2], eqB[3]));
                const float2 fA = __half22float2(rA);
                const float2 fB = __half22float2(rB);
                aA0 += fA.x; aA1 += fA.y;
                aB0 += fB.x; aB1 += fB.y;
            }
            // fp32 scalar-S butterflies (latency hidden by 6 warps/SMSP)
            lse_up(mA, sA, mred8(tCA, lane));
            lse_up(mB, sB, mred8(tCB, lane));
        }

        ((float2*)g_psum)[(i0 * NCHUNK + c) * 32 + lane]       = make_float2(aA0, aA1);
        ((float2*)g_psum)[((i0 + 1) * NCHUNK + c) * 32 + lane] = make_float2(aB0, aB1);
        merge_classes(mA, sA);
        merge_classes(mB, sB);
        if (lane == 0) {
            g_pm[i0 * NCHUNK + c] = mA;
            g_ps[i0 * NCHUNK + c] = sA;
            g_pm[(i0 + 1) * NCHUNK + c] = mB;
            g_ps[(i0 + 1) * NCHUNK + c] = sB;
        }
    }
}

// k2: one warp per i combines the 32 chunk partials.
__global__ __launch_bounds__(256)
void tc_reduce_i()
{
    const int wid  = threadIdx.x >> 5;
    const int lane = threadIdx.x & 31;
    const int i    = blockIdx.x * 8 + wid;

    float s0 = 0.f, s1 = 0.f;
    const float2* P = (const float2*)g_psum;
    #pragma unroll
    for (int cc = 0; cc < NCHUNK; ++cc) {
        const float2 v = P[(i * NCHUNK + cc) * 32 + lane];
        s0 += v.x; s1 += v.y;
    }
    float t = lg2f(s0) + lg2f(s1);
    #pragma unroll
    for (int off = 16; off; off >>= 1)
        t += __shfl_xor_sync(0xffffffffu, t, off);

    float ml = g_pm[i * NCHUNK + lane];   // NCHUNK==32: one chunk per lane
    float sl = g_ps[i * NCHUNK + lane];
    #pragma unroll
    for (int off = 16; off; off >>= 1) {
        const float mo = __shfl_xor_sync(0xffffffffu, ml, off);
        const float so = __shfl_xor_sync(0xffffffffu, sl, off);
        const float M  = fmaxf(ml, mo);
        sl = sl * ex2f(ml - M) + so * ex2f(mo - M);
        ml = M;
    }

    if (lane == 0)
        g_val[i] = LN2 * (t - (ml + lg2f(sl)));
}

// k3: deterministic final mean (256 threads, shuffle-based).
__global__ __launch_bounds__(256)
void tc_final(float* __restrict__ out)
{
    __shared__ float sm[8];
    const int t = threadIdx.x;
    float v = 0.f;
    #pragma unroll
    for (int k = 0; k < 8; ++k)
        v += g_val[t + k * 256];
    #pragma unroll
    for (int off = 16; off; off >>= 1)
        v += __shfl_xor_sync(0xffffffffu, v, off);
    if ((t & 31) == 0) sm[t >> 5] = v;
    __syncthreads();
    if (t == 0) {
        float r = 0.f;
        #pragma unroll
        for (int k = 0; k < 8; ++k) r += sm[k];
        out[0] = r * (1.0f / (float)NPTS);
    }
}

extern "C" void kernel_launch(void* const* d_in, const int* in_sizes, int n_in,
                              void* d_out, int out_size)
{
    const float* z  = (const float*)d_in[0];
    const float* zm = (const float*)d_in[1];
    const float* zl = (const float*)d_in[2];
    tc_coeff_kernel<<<NPTS * DDIM / 1024, 256>>>(zm, zl);
    tc_main_kernel<<<NBLOCKS, 256>>>(z);
    tc_reduce_i<<<NPTS / 8, 256>>>();
    tc_final<<<1, 256>>>((float*)d_out);
}

// round 11
// speedup vs baseline: 1.3205x; 1.1619x over previous
#include <cuda_runtime.h>
#include <cuda_fp16.h>

// TCLoss, N=2048, D=64.
// y_ijd = LOG2E * log N(z_i,d ; m_j,d, exp(lv_j,d)) = a_jd*z^2 + b_jd*z + g_jd
// out = mean_i [ LN2*( sum_d log2 sum_j 2^y  -  log2sumexp2_j sum_d y ) ]
//
// k0: precompute coeffs (AB float4 (a0,a1,b0,b1), G float2 per (j,dim-pair)).
// k1: persistent main (R6 structure, 2 blocks/SM, software pipeline).
//     Warp owns 2 i's, lane owns dims {2l,2l+1}; 64-j smem tile. y in fp32
//     FMA. Per-dim exps via ex2.approx.f16x2, half2 pair accumulation, fp32
//     flush each 8-j batch. Scalar S path: ROTATED multi-value butterfly —
//     lane l's register k holds j-class k^((l>>2)&7), which makes the
//     cross-register routing a pure shfl_xor+add (no SELs): 9 SHFL + 9 FADD
//     per 8 classes. Per-lane fp32 online LSE, class-merged once per unit.
// k2: per-i reduction over 32 chunk partials. k3: mean.

#define LOG2E   1.44269504088896340736f
#define LN2     0.69314718055994530942f
#define LOG2PI  1.83787706640934548356f
#define NEG_INF __int_as_float(0xff800000)

#define NPTS    2048
#define DDIM    64
#define TJ      64                   // j's per chunk
#define NCHUNK  (NPTS / TJ)          // 32
#define IPB     16                   // i's per block (8 warps x 2)
#define NGROUP  (NPTS / IPB)         // 128
#define NUNITS  (NGROUP * NCHUNK)    // 4096
#define NBLOCKS 296                  // 148 SMs x 2 resident blocks

// Static scratch (no allocation).
__device__ float4 g_cAB[NPTS * DDIM / 2];       // (a0,a1,b0,b1) per (j, dim-pair)
__device__ float2 g_cG[NPTS * DDIM / 2];        // (g0,g1) per (j, dim-pair)
__device__ float g_psum[NPTS * NCHUNK * DDIM];  // per-(i,chunk) per-dim sums of 2^y
__device__ float g_pm[NPTS * NCHUNK];           // per-(i,chunk) LSE max (log2)
__device__ float g_ps[NPTS * NCHUNK];           // per-(i,chunk) LSE scaled sum
__device__ float g_val[NPTS];                   // per-i result

static __device__ __forceinline__ float ex2f(float x) {
    float r; asm("ex2.approx.ftz.f32 %0, %1;" : "=f"(r) : "f"(x)); return r;
}
static __device__ __forceinline__ float lg2f(float x) {
    float r; asm("lg2.approx.f32 %0, %1;" : "=f"(r) : "f"(x)); return r;
}
// Pack two fp32 -> half2 (single F2FP.PACK), then 2^x on both halves (1 MUFU).
static __device__ __forceinline__ __half2 ex2h2(float x, float y) {
    __half2 h = __floats2half2_rn(x, y);
    __half2 r;
    asm("ex2.approx.f16x2 %0, %1;"
        : "=r"(*reinterpret_cast<unsigned*>(&r))
        : "r"(*reinterpret_cast<const unsigned*>(&h)));
    return r;
}

// Online base-2 logsumexp update with a single EX2.
static __device__ __forceinline__ void lse_up(float& m, float& s, float S) {
    const float d = S - m;
    const float e = ex2f(-fabsf(d));   // ex2(-inf)=0 handles first call (m=-inf)
    if (d > 0.f) { s = fmaf(s, e, 1.f); m = S; }
    else         { s += e; }
}

// Rotated multi-value warp reduction: lane l's t[k] holds the partial for
// j-class (k ^ sigma), sigma = (l>>2)&7. Because peers at xor-distance 16/8/4
// have sigma differing in exactly the bit that register-xor 4/2/1 encodes,
// the routing needs NO selects:
//   level 16: t[k] += shfl_xor(t[k^4],16)   (peer's reg k^4 holds my class)
//   level  8: t[k] += shfl_xor(t[k^2], 8)
//   level  4: t[0] += shfl_xor(t[1],   4)
//   levels 2,1: plain butterfly (same sigma).
// Returns, on every lane, the full 32-lane sum of class (lane>>2)&7.
static __device__ __forceinline__ float mred8rot(float t[8]) {
    #pragma unroll
    for (int k = 0; k < 4; ++k)
        t[k] += __shfl_xor_sync(0xffffffffu, t[k ^ 4], 16);
    #pragma unroll
    for (int k = 0; k < 2; ++k)
        t[k] += __shfl_xor_sync(0xffffffffu, t[k ^ 2], 8);
    t[0] += __shfl_xor_sync(0xffffffffu, t[1], 4);
    float v = t[0];
    v += __shfl_xor_sync(0xffffffffu, v, 2);
    v += __shfl_xor_sync(0xffffffffu, v, 1);
    return v;
}

// Merge per-lane (m,s) across the 8 j-classes (lane bits 2..4).
static __device__ __forceinline__ void merge_classes(float& m, float& s) {
    #pragma unroll
    for (int off = 4; off <= 16; off <<= 1) {
        const float mo = __shfl_xor_sync(0xffffffffu, m, off);
        const float so = __shfl_xor_sync(0xffffffffu, s, off);
        const float M  = fmaxf(m, mo);
        s = s * ex2f(m - M) + so * ex2f(mo - M);
        m = M;
    }
}

static __device__ __forceinline__ void coeffs(float mm, float lv,
                                              float& a, float& b, float& g) {
    const float iv = ex2f(-LOG2E * lv);          // exp(-lv)
    const float w  = -0.5f * LOG2E * iv;
    const float t  = w * mm;
    a = w;
    b = -(t + t);
    g = fmaf(t, mm, -0.5f * LOG2E * (lv + LOG2PI));
}

// k0: precompute packed coefficient arrays.
__global__ __launch_bounds__(256)
void tc_coeff_kernel(const float* __restrict__ zmean, const float* __restrict__ zlv)
{
    const int e = blockIdx.x * 256 + threadIdx.x;   // [0, 32768)
    const int j = e >> 4;
    const int f = e & 15;                           // float4 index within row
    const float4 mv = ((const float4*)zmean)[e];
    const float4 lv = ((const float4*)zlv)[e];
    float a0, b0, g0, a1, b1, g1, a2, b2, g2, a3, b3, g3;
    coeffs(mv.x, lv.x, a0, b0, g0);
    coeffs(mv.y, lv.y, a1, b1, g1);
    coeffs(mv.z, lv.z, a2, b2, g2);
    coeffs(mv.w, lv.w, a3, b3, g3);
    g_cAB[(j << 5) + 2 * f]     = make_float4(a0, a1, b0, b1);
    g_cAB[(j << 5) + 2 * f + 1] = make_float4(a2, a3, b2, b3);
    g_cG[(j << 5) + 2 * f]      = make_float2(g0, g1);
    g_cG[(j << 5) + 2 * f + 1]  = make_float2(g2, g3);
}

// k1: main pairwise kernel.
__global__ __launch_bounds__(256, 2)
void tc_main_kernel(const float* __restrict__ z)
{
    __shared__ float4 shAB[TJ * 32];   // 32 KB
    __shared__ float2 shG[TJ * 32];    // 16 KB

    const int tid  = threadIdx.x;
    const int wid  = tid >> 5;
    const unsigned lane = tid & 31;
    const unsigned sig  = (lane >> 2) & 7;   // rotation for SEL-free butterfly

    for (int u = blockIdx.x; u < NUNITS; u += NBLOCKS) {
        const int ig = u & (NGROUP - 1);
        const int c  = u >> 7;
        const int js = c * TJ;

        __syncthreads();  // previous unit's readers done
        {
            const float4* pab = g_cAB + js * 32;
            const float4* pg  = (const float4*)(g_cG + js * 32);
            #pragma unroll
            for (int e = tid; e < TJ * 32; e += 256)
                shAB[e] = pab[e];
            #pragma unroll
            for (int e = tid; e < TJ * 16; e += 256)
                ((float4*)shG)[e] = pg[e];
        }
        __syncthreads();

        const int i0 = ig * IPB + wid * 2;
        const float2 zva = ((const float2*)z)[i0 * 32 + lane];
        const float2 zvb = ((const float2*)z)[(i0 + 1) * 32 + lane];
        const float zA0 = zva.x, zA1 = zva.y, zB0 = zvb.x, zB1 = zvb.y;
        const float qA0 = zA0 * zA0, qA1 = zA1 * zA1;
        const float qB0 = zB0 * zB0, qB1 = zB1 * zB1;

        float aA0 = 0.f, aA1 = 0.f, aB0 = 0.f, aB1 = 0.f;
        float mA = NEG_INF, sA = 0.f, mB = NEG_INF, sB = 0.f;

        float tPA[8], tPB[8];   // previous batch's scalar partials (rotated)

        // Software pipeline: compute batch jb, then reduce batch jb-1.
        #pragma unroll
        for (int jb = 0; jb < TJ / 8; ++jb) {
            float tCA[8], tCB[8];
            __half2 eqA[4], eqB[4];    // pairwise half2 exp accumulators
            #pragma unroll
            for (int k = 0; k < 8; ++k) {
                // rotated class assignment: this lane's register k covers
                // j-class k^sig of the batch.
                const int j = jb * 8 + (k ^ (int)sig);
                const float4 ab = shAB[j * 32 + lane];
                const float2 g  = shG[j * 32 + lane];
                const float yA0 = fmaf(ab.x, qA0, fmaf(ab.z, zA0, g.x));
                const float yA1 = fmaf(ab.y, qA1, fmaf(ab.w, zA1, g.y));
                const float yB0 = fmaf(ab.x, qB0, fmaf(ab.z, zB0, g.x));
                const float yB1 = fmaf(ab.y, qB1, fmaf(ab.w, zB1, g.y));
                const __half2 eA = ex2h2(yA0, yA1);
                const __half2 eB = ex2h2(yB0, yB1);
                if (k & 1) {
                    eqA[k >> 1] = __hadd2(eqA[k >> 1], eA);
                    eqB[k >> 1] = __hadd2(eqB[k >> 1], eB);
                } else {
                    eqA[k >> 1] = eA;
                    eqB[k >> 1] = eB;
                }
                tCA[k] = yA0 + yA1;
                tCB[k] = yB0 + yB1;
            }
            // tree-flush half2 exp partials to fp32 accumulators
            {
                const __half2 rA = __hadd2(__hadd2(eqA[0], eqA[1]),
                                           __hadd2(eqA[2], eqA[3]));
                const __half2 rB = __hadd2(__hadd2(eqB[0], eqB[1]),
                                           __hadd2(eqB[2], eqB[3]));
                const float2 fA = __half22float2(rA);
                const float2 fB = __half22float2(rB);
                aA0 += fA.x; aA1 += fA.y;
                aB0 += fB.x; aB1 += fB.y;
            }
            if (jb > 0) {
                lse_up(mA, sA, mred8rot(tPA));
                lse_up(mB, sB, mred8rot(tPB));
            }
            #pragma unroll
            for (int k = 0; k < 8; ++k) { tPA[k] = tCA[k]; tPB[k] = tCB[k]; }
        }
        lse_up(mA, sA, mred8rot(tPA));
        lse_up(mB, sB, mred8rot(tPB));

        ((float2*)g_psum)[(i0 * NCHUNK + c) * 32 + lane]       = make_float2(aA0, aA1);
        ((float2*)g_psum)[((i0 + 1) * NCHUNK + c) * 32 + lane] = make_float2(aB0, aB1);
        merge_classes(mA, sA);
        merge_classes(mB, sB);
        if (lane == 0) {
            g_pm[i0 * NCHUNK + c] = mA;
            g_ps[i0 * NCHUNK + c] = sA;
            g_pm[(i0 + 1) * NCHUNK + c] = mB;
            g_ps[(i0 + 1) * NCHUNK + c] = sB;
        }
    }
}

// k2: one warp per i combines the 32 chunk partials.
__global__ __launch_bounds__(256)
void tc_reduce_i()
{
    const int wid  = threadIdx.x >> 5;
    const int lane = threadIdx.x & 31;
    const int i    = blockIdx.x * 8 + wid;

    float s0 = 0.f, s1 = 0.f;
    const float2* P = (const float2*)g_psum;
    #pragma unroll
    for (int cc = 0; cc < NCHUNK; ++cc) {
        const float2 v = P[(i * NCHUNK + cc) * 32 + lane];
        s0 += v.x; s1 += v.y;
    }
    float t = lg2f(s0) + lg2f(s1);
    #pragma unroll
    for (int off = 16; off; off >>= 1)
        t += __shfl_xor_sync(0xffffffffu, t, off);

    float ml = g_pm[i * NCHUNK + lane];   // NCHUNK==32: one chunk per lane
    float sl = g_ps[i * NCHUNK + lane];
    #pragma unroll
    for (int off = 16; off; off >>= 1) {
        const float mo = __shfl_xor_sync(0xffffffffu, ml, off);
        const float so = __shfl_xor_sync(0xffffffffu, sl, off);
        const float M  = fmaxf(ml, mo);
        sl = sl * ex2f(ml - M) + so * ex2f(mo - M);
        ml = M;
    }

    if (lane == 0)
        g_val[i] = LN2 * (t - (ml + lg2f(sl)));
}

// k3: deterministic final mean (256 threads, shuffle-based).
__global__ __launch_bounds__(256)
void tc_final(float* __restrict__ out)
{
    __shared__ float sm[8];
    const int t = threadIdx.x;
    float v = 0.f;
    #pragma unroll
    for (int k = 0; k < 8; ++k)
        v += g_val[t + k * 256];
    #pragma unroll
    for (int off = 16; off; off >>= 1)
        v += __shfl_xor_sync(0xffffffffu, v, off);
    if ((t & 31) == 0) sm[t >> 5] = v;
    __syncthreads();
    if (t == 0) {
        float r = 0.f;
        #pragma unroll
        for (int k = 0; k < 8; ++k) r += sm[k];
        out[0] = r * (1.0f / (float)NPTS);
    }
}

extern "C" void kernel_launch(void* const* d_in, const int* in_sizes, int n_in,
                              void* d_out, int out_size)
{
    const float* z  = (const float*)d_in[0];
    const float* zm = (const float*)d_in[1];
    const float* zl = (const float*)d_in[2];
    tc_coeff_kernel<<<NPTS * DDIM / 1024, 256>>>(zm, zl);
    tc_main_kernel<<<NBLOCKS, 256>>>(z);
    tc_reduce_i<<<NPTS / 8, 256>>>();
    tc_final<<<1, 256>>>((float*)d_out);
}